// round 1
// baseline (speedup 1.0000x reference)
#include <cuda_runtime.h>
#include <cuda_bf16.h>
#include <cstdint>

#define N_NODES 50000
#define N_GRAPHS 128
#define DH 64
#define DOUT 16

// -------- static device scratch (no allocations allowed) --------
__device__ float g_agg[(size_t)N_NODES * DH];
__device__ float g_h1[(size_t)N_NODES * DH];
__device__ float g_h2[(size_t)N_NODES * DH];
__device__ float g_pooled[N_GRAPHS * DH];
__device__ float g_counts[N_GRAPHS];

// ---------------- scatter: agg[dst] += x[src] -------------------
// 16 lanes per edge, each lane handles one float4 (4 cols) of the 64-wide row.
__global__ void scatter_kernel(const float* __restrict__ xin,
                               const int* __restrict__ ei,
                               int ne,
                               float* __restrict__ agg) {
    int tid = blockIdx.x * blockDim.x + threadIdx.x;
    int e = tid >> 4;
    int lane = tid & 15;
    if (e >= ne) return;
    int s = __ldg(&ei[e]);
    int d = __ldg(&ei[ne + e]);
    float4 v = ((const float4*)(xin + (size_t)s * DH))[lane];
    float* dst = agg + (size_t)d * DH + lane * 4;
    asm volatile("red.global.add.v4.f32 [%0], {%1,%2,%3,%4};"
                 :: "l"(dst), "f"(v.x), "f"(v.y), "f"(v.z), "f"(v.w)
                 : "memory");
}

// -------- fused layer GEMM: out = agg@Wrel + x@Wroot + b (opt ReLU) --------
// Block: 256 threads (16x16), tile 64 rows x 64 cols, thread tile 4x4.
__global__ void gemm_fused_kernel(const float* __restrict__ A,     // agg [N,64]
                                  const float* __restrict__ X,     // x   [N,64]
                                  const float* __restrict__ Wrel,  // [64,64]
                                  const float* __restrict__ brel,  // [64]
                                  const float* __restrict__ Wroot, // [64,64]
                                  float* __restrict__ out,
                                  int do_relu) {
    __shared__ float sW[64][64];
    __shared__ float sA[64][68];  // pad to 68 -> conflict-free column reads

    int tx = threadIdx.x & 15;   // col group
    int ty = threadIdx.x >> 4;   // row group
    int rowBase = blockIdx.x * 64;

    float acc[4][4] = {};

    #pragma unroll
    for (int p = 0; p < 2; ++p) {
        const float* M = p ? X : A;
        const float* W = p ? Wroot : Wrel;

        __syncthreads();  // protect previous pass's smem reads

        // load W (4096 floats) as float4s: 1024 float4 / 256 threads = 4 each
        #pragma unroll
        for (int i = threadIdx.x; i < 1024; i += 256) {
            ((float4*)&sW[0][0])[i] = ((const float4*)W)[i];
        }
        // load 64x64 input tile
        #pragma unroll
        for (int i = threadIdx.x; i < 1024; i += 256) {
            int r  = i >> 4;
            int c4 = i & 15;
            int gr = rowBase + r;
            float4 v = (gr < N_NODES)
                     ? ((const float4*)(M + (size_t)gr * DH))[c4]
                     : make_float4(0.f, 0.f, 0.f, 0.f);
            sA[r][c4 * 4 + 0] = v.x;
            sA[r][c4 * 4 + 1] = v.y;
            sA[r][c4 * 4 + 2] = v.z;
            sA[r][c4 * 4 + 3] = v.w;
        }
        __syncthreads();

        #pragma unroll 16
        for (int k = 0; k < 64; ++k) {
            float4 bv = *(const float4*)&sW[k][tx * 4];
            float a0 = sA[ty * 4 + 0][k];
            float a1 = sA[ty * 4 + 1][k];
            float a2 = sA[ty * 4 + 2][k];
            float a3 = sA[ty * 4 + 3][k];
            acc[0][0] += a0 * bv.x; acc[0][1] += a0 * bv.y; acc[0][2] += a0 * bv.z; acc[0][3] += a0 * bv.w;
            acc[1][0] += a1 * bv.x; acc[1][1] += a1 * bv.y; acc[1][2] += a1 * bv.z; acc[1][3] += a1 * bv.w;
            acc[2][0] += a2 * bv.x; acc[2][1] += a2 * bv.y; acc[2][2] += a2 * bv.z; acc[2][3] += a2 * bv.w;
            acc[3][0] += a3 * bv.x; acc[3][1] += a3 * bv.y; acc[3][2] += a3 * bv.z; acc[3][3] += a3 * bv.w;
        }
    }

    float4 bb = *(const float4*)&brel[tx * 4];
    #pragma unroll
    for (int i = 0; i < 4; ++i) {
        int gr = rowBase + ty * 4 + i;
        if (gr < N_NODES) {
            float4 o;
            o.x = acc[i][0] + bb.x;
            o.y = acc[i][1] + bb.y;
            o.z = acc[i][2] + bb.z;
            o.w = acc[i][3] + bb.w;
            if (do_relu) {
                o.x = fmaxf(o.x, 0.f); o.y = fmaxf(o.y, 0.f);
                o.z = fmaxf(o.z, 0.f); o.w = fmaxf(o.w, 0.f);
            }
            *(float4*)(out + (size_t)gr * DH + tx * 4) = o;
        }
    }
}

// ---------------- pooling: sums + counts via red.global ----------------
__global__ void pool_kernel(const float* __restrict__ h,
                            const int* __restrict__ batch,
                            float* __restrict__ pooled,
                            float* __restrict__ counts) {
    int tid = blockIdx.x * blockDim.x + threadIdx.x;
    int n = tid >> 4;
    int lane = tid & 15;
    if (n >= N_NODES) return;
    int g = __ldg(&batch[n]);
    float4 v = ((const float4*)(h + (size_t)n * DH))[lane];
    float* dst = pooled + g * DH + lane * 4;
    asm volatile("red.global.add.v4.f32 [%0], {%1,%2,%3,%4};"
                 :: "l"(dst), "f"(v.x), "f"(v.y), "f"(v.z), "f"(v.w)
                 : "memory");
    if (lane == 0) {
        atomicAdd(&counts[g], 1.0f);
    }
}

// --------------- head: out = (pooled/count) @ W_lin + b_lin -------------
__global__ void head_kernel(const float* __restrict__ pooled,
                            const float* __restrict__ counts,
                            const float* __restrict__ Wlin,  // [64,16]
                            const float* __restrict__ blin,  // [16]
                            float* __restrict__ out) {
    int tid = blockIdx.x * blockDim.x + threadIdx.x;
    if (tid >= N_GRAPHS * DOUT) return;
    int g = tid >> 4;
    int o = tid & 15;
    float c = counts[g];
    c = c < 1.0f ? 1.0f : c;
    float s = 0.f;
    #pragma unroll
    for (int k = 0; k < DH; ++k) {
        s += pooled[g * DH + k] * Wlin[k * DOUT + o];
    }
    out[g * DOUT + o] = s / c + blin[o];
}

extern "C" void kernel_launch(void* const* d_in, const int* in_sizes, int n_in,
                              void* d_out, int out_size) {
    const float* x      = (const float*)d_in[0];
    const int*   ei     = (const int*)d_in[1];
    // d_in[2] = adj (unused)
    const int*   batch  = (const int*)d_in[3];
    const float* Wrel1  = (const float*)d_in[4];
    const float* brel1  = (const float*)d_in[5];
    const float* Wroot1 = (const float*)d_in[6];
    const float* Wrel2  = (const float*)d_in[7];
    const float* brel2  = (const float*)d_in[8];
    const float* Wroot2 = (const float*)d_in[9];
    const float* Wrel3  = (const float*)d_in[10];
    const float* brel3  = (const float*)d_in[11];
    const float* Wroot3 = (const float*)d_in[12];
    const float* Wlin   = (const float*)d_in[13];
    const float* blin   = (const float*)d_in[14];
    float* out = (float*)d_out;

    int ne = in_sizes[1] / 2;

    void *agg_p, *h1_p, *h2_p, *pooled_p, *counts_p;
    cudaGetSymbolAddress(&agg_p, g_agg);
    cudaGetSymbolAddress(&h1_p, g_h1);
    cudaGetSymbolAddress(&h2_p, g_h2);
    cudaGetSymbolAddress(&pooled_p, g_pooled);
    cudaGetSymbolAddress(&counts_p, g_counts);

    float* agg = (float*)agg_p;
    float* h1 = (float*)h1_p;
    float* h2 = (float*)h2_p;
    float* pooled = (float*)pooled_p;
    float* counts = (float*)counts_p;

    const size_t AGG_BYTES = (size_t)N_NODES * DH * sizeof(float);
    int scatterBlocks = (ne * 16 + 255) / 256;
    int gemmBlocks = (N_NODES + 63) / 64;
    int poolBlocks = (N_NODES * 16 + 255) / 256;

    // ---- layer 1: x -> h1 (ReLU) ----
    cudaMemsetAsync(agg, 0, AGG_BYTES, 0);
    scatter_kernel<<<scatterBlocks, 256>>>(x, ei, ne, agg);
    gemm_fused_kernel<<<gemmBlocks, 256>>>(agg, x, Wrel1, brel1, Wroot1, h1, 1);

    // ---- layer 2: h1 -> h2 (ReLU) ----
    cudaMemsetAsync(agg, 0, AGG_BYTES, 0);
    scatter_kernel<<<scatterBlocks, 256>>>(h1, ei, ne, agg);
    gemm_fused_kernel<<<gemmBlocks, 256>>>(agg, h1, Wrel2, brel2, Wroot2, h2, 1);

    // ---- layer 3: h2 -> h1 (no ReLU) ----
    cudaMemsetAsync(agg, 0, AGG_BYTES, 0);
    scatter_kernel<<<scatterBlocks, 256>>>(h2, ei, ne, agg);
    gemm_fused_kernel<<<gemmBlocks, 256>>>(agg, h2, Wrel3, brel3, Wroot3, h1, 0);

    // ---- pooling + head ----
    cudaMemsetAsync(pooled, 0, N_GRAPHS * DH * sizeof(float), 0);
    cudaMemsetAsync(counts, 0, N_GRAPHS * sizeof(float), 0);
    pool_kernel<<<poolBlocks, 256>>>(h1, batch, pooled, counts);
    head_kernel<<<(N_GRAPHS * DOUT + 255) / 256, 256>>>(pooled, counts, Wlin, blin, out);
}